// round 2
// baseline (speedup 1.0000x reference)
#include <cuda_runtime.h>
#include <math.h>

#define TPB 256

// Partial per-row sums (B <= 65536 supported; actual B = 16384).
__device__ float g_partials[65536];

__device__ __forceinline__ float warp_sum(float v) {
#pragma unroll
    for (int o = 16; o > 0; o >>= 1) v += __shfl_xor_sync(0xffffffffu, v, o);
    return v;
}
__device__ __forceinline__ float warp_max(float v) {
#pragma unroll
    for (int o = 16; o > 0; o >>= 1) v = fmaxf(v, __shfl_xor_sync(0xffffffffu, v, o));
    return v;
}

// Block reductions over TPB=256 threads (8 warps). sred must be 8 floats.
__device__ __forceinline__ float block_sum(float v, float* sred) {
    int tid = threadIdx.x;
    v = warp_sum(v);
    __syncthreads();                 // protect sred reuse across calls
    if ((tid & 31) == 0) sred[tid >> 5] = v;
    __syncthreads();
    float r = sred[0];
#pragma unroll
    for (int i = 1; i < TPB / 32; i++) r += sred[i];
    return r;
}
__device__ __forceinline__ float block_max(float v, float* sred) {
    int tid = threadIdx.x;
    v = warp_max(v);
    __syncthreads();
    if ((tid & 31) == 0) sred[tid >> 5] = v;
    __syncthreads();
    float r = sred[0];
#pragma unroll
    for (int i = 1; i < TPB / 32; i++) r = fmaxf(r, sred[i]);
    return r;
}

__device__ __forceinline__ float loss_elem(float x, float m, float logsum,
                                           float e, float inv_s, float y) {
    const float EPSF  = 1e-7f;
    const float ONEM  = 1.0f - 1e-7f;
    float t = (x - m) - logsum;        // log p (unclipped), free
    float p = e * inv_s;               // softmax prob
    float pc = fminf(fmaxf(p, EPSF), ONEM);
    float logp = (p >= EPSF && p <= ONEM) ? t : __logf(pc);
    // log1p(-pc): polynomial for small pc (always taken for this data),
    // exact-ish fallback otherwise.
    float l1m;
    if (pc < 0.04f) {
        l1m = -pc * (1.0f + pc * (0.5f + pc * (0.33333334f + pc * 0.25f)));
    } else {
        l1m = __logf(1.0f - pc);
    }
    // accumulate +(y*logp + (1-y)*l1m); negate once per row
    return fmaf(y, logp, (1.0f - y) * l1m);
}

// Fast path: C == 4096, one block of 256 threads per row, 16 elems/thread in regs.
__global__ void __launch_bounds__(TPB)
wvce_row4096(const float* __restrict__ y_pred, const float* __restrict__ y_true,
             const float* __restrict__ weights, const int* __restrict__ cond,
             int nbins) {
    const int C = 4096;
    int row = blockIdx.x;
    int tid = threadIdx.x;
    const float4* xp = (const float4*)(y_pred + (size_t)row * C);
    const float4* yp = (const float4*)(y_true + (size_t)row * C);

    __shared__ float sred[TPB / 32];

    float4 x[4];
    float lmax = -INFINITY;
#pragma unroll
    for (int k = 0; k < 4; k++) {
        x[k] = xp[tid + k * TPB];
        lmax = fmaxf(lmax, fmaxf(fmaxf(x[k].x, x[k].y), fmaxf(x[k].z, x[k].w)));
    }
    float m = block_max(lmax, sred);

    float4 e[4];
    float lsum = 0.0f;
#pragma unroll
    for (int k = 0; k < 4; k++) {
        e[k].x = __expf(x[k].x - m);
        e[k].y = __expf(x[k].y - m);
        e[k].z = __expf(x[k].z - m);
        e[k].w = __expf(x[k].w - m);
        lsum += (e[k].x + e[k].y) + (e[k].z + e[k].w);
    }
    float s = block_sum(lsum, sred);
    float logsum = __logf(s);
    float inv_s = 1.0f / s;

    float acc = 0.0f;
#pragma unroll
    for (int k = 0; k < 4; k++) {
        float4 y4 = yp[tid + k * TPB];
        acc += loss_elem(x[k].x, m, logsum, e[k].x, inv_s, y4.x);
        acc += loss_elem(x[k].y, m, logsum, e[k].y, inv_s, y4.y);
        acc += loss_elem(x[k].z, m, logsum, e[k].z, inv_s, y4.z);
        acc += loss_elem(x[k].w, m, logsum, e[k].w, inv_s, y4.w);
    }
    float rowsum = block_sum(acc, sred);
    if (tid == 0) {
        int bi = cond[row];
        bi = max(0, min(bi, nbins - 1));     // clamp: never fault on bad data
        float w = weights[bi];
        g_partials[row] = -w * rowsum;
    }
}

// Generic fallback (any C): 3 passes re-reading gmem. Correctness safety net.
__global__ void __launch_bounds__(TPB)
wvce_row_generic(const float* __restrict__ y_pred, const float* __restrict__ y_true,
                 const float* __restrict__ weights, const int* __restrict__ cond,
                 int C, int nbins) {
    int row = blockIdx.x;
    int tid = threadIdx.x;
    const float* xp = y_pred + (size_t)row * C;
    const float* yp = y_true + (size_t)row * C;
    __shared__ float sred[TPB / 32];

    float lmax = -INFINITY;
    for (int i = tid; i < C; i += TPB) lmax = fmaxf(lmax, xp[i]);
    float m = block_max(lmax, sred);

    float lsum = 0.0f;
    for (int i = tid; i < C; i += TPB) lsum += __expf(xp[i] - m);
    float s = block_sum(lsum, sred);
    float logsum = __logf(s);
    float inv_s = 1.0f / s;

    float acc = 0.0f;
    for (int i = tid; i < C; i += TPB) {
        float x = xp[i];
        float e = __expf(x - m);
        acc += loss_elem(x, m, logsum, e, inv_s, yp[i]);
    }
    float rowsum = block_sum(acc, sred);
    if (tid == 0) {
        int bi = cond[row];
        bi = max(0, min(bi, nbins - 1));
        float w = weights[bi];
        g_partials[row] = -w * rowsum;
    }
}

// Final deterministic reduce: 1 block, double accumulation, mean over B*C.
__global__ void __launch_bounds__(TPB)
wvce_final(float* __restrict__ out, int B, int C) {
    __shared__ double sd[TPB];
    double a = 0.0;
    for (int i = threadIdx.x; i < B; i += TPB) a += (double)g_partials[i];
    sd[threadIdx.x] = a;
    __syncthreads();
#pragma unroll
    for (int s = TPB / 2; s > 0; s >>= 1) {
        if (threadIdx.x < s) sd[threadIdx.x] += sd[threadIdx.x + s];
        __syncthreads();
    }
    if (threadIdx.x == 0)
        out[0] = (float)(sd[0] / ((double)B * (double)C));
}

extern "C" void kernel_launch(void* const* d_in, const int* in_sizes, int n_in,
                              void* d_out, int out_size) {
    const float* y_pred  = (const float*)d_in[0];
    const float* y_true  = (const float*)d_in[1];
    const float* weights = (const float*)d_in[2];
    const int*   cond    = (const int*)d_in[3];   // JAX x64 disabled -> int32

    int B     = in_sizes[3];
    int nbins = in_sizes[2];
    int C     = in_sizes[0] / B;

    if (C == 4096) {
        wvce_row4096<<<B, TPB>>>(y_pred, y_true, weights, cond, nbins);
    } else {
        wvce_row_generic<<<B, TPB>>>(y_pred, y_true, weights, cond, C, nbins);
    }
    wvce_final<<<1, TPB>>>((float*)d_out, B, C);
}